// round 16
// baseline (speedup 1.0000x reference)
#include <cuda_runtime.h>
#include <cuda_bf16.h>

#define LOG2E 1.4426950408889634f

#define NCHK 32
#define CHKL 32

typedef unsigned long long u64;

// ---------------- scratch (__device__ globals; no allocation allowed) -------
__device__ float g_xn  [32*1024*64];
__device__ float g_z   [32*1024*128];
__device__ float g_xc  [32*1024*128];
__device__ float g_dt  [32*1024*128];
__device__ float g_Bm  [32*1024*16];
__device__ float g_Cm  [32*1024*16];
__device__ float g_pend[32*NCHK*128*16];
__device__ float g_dtot[32*NCHK*128*16];
__device__ float g_h0  [32*NCHK*128*16];

__device__ __forceinline__ float ex2f(float x) {
    float r; asm("ex2.approx.f32 %0, %1;" : "=f"(r) : "f"(x)); return r;
}
__device__ __forceinline__ float siluf(float x) {
    return x / (1.0f + __expf(-x));
}
__device__ __forceinline__ float softplusf(float x) {
    return fmaxf(x, 0.f) + __logf(1.0f + __expf(-fabsf(x)));
}
__device__ __forceinline__ u64 fma2(u64 a, u64 b, u64 c) {
    u64 d; asm("fma.rn.f32x2 %0, %1, %2, %3;" : "=l"(d) : "l"(a), "l"(b), "l"(c)); return d;
}
__device__ __forceinline__ u64 mul2(u64 a, u64 b) {
    u64 d; asm("mul.rn.f32x2 %0, %1, %2;" : "=l"(d) : "l"(a), "l"(b)); return d;
}
__device__ __forceinline__ u64 pack2(float x, float y) {
    u64 r; asm("mov.b64 %0, {%1, %2};" : "=l"(r) : "f"(x), "f"(y)); return r;
}
__device__ __forceinline__ void unpack2(u64 v, float& x, float& y) {
    asm("mov.b64 {%0, %1}, %2;" : "=f"(x), "=f"(y) : "l"(v));
}
__device__ __forceinline__ float hsum2(u64 v) {
    float x, y; unpack2(v, x, y); return x + y;
}
__device__ __forceinline__ bool ratio_fast(const float* a2) {
    bool ok = true;
    #pragma unroll
    for (int s = 1; s < 16; s++) {
        float want = (float)(s + 1) * a2[0];
        ok = ok && (fabsf(a2[s] - want) <= 1e-3f * fabsf(want));
    }
    return ok;
}
// dA[s] = p^(s+1): exponents of dA[(s-1)>>1] and dA[s>>1] sum to s+1
__device__ __forceinline__ void powers16(float p, float* dA) {
    dA[0] = p;
    #pragma unroll
    for (int s = 1; s < 16; s++) dA[s] = dA[(s-1) >> 1] * dA[s >> 1];
}

// kA smem layout (floats). Two phase-disjoint views of the low region:
//   GEMM phase : xs [35][68] | stat | Wq [64][68]
//   xproj phase: Wxp [36][132] | res36 [32][36]
// xis [35][128] lives above both.
#define XS_PITCH 68
#define XI_PITCH 128
#define OFF_XS    0
#define OFF_STAT  2380
#define OFF_WQ    2452
#define OFF_WX    0
#define OFF_R36   4752
#define OFF_XIS   6804
#define SMEMA_FLOATS (OFF_XIS + 35*XI_PITCH)   // 11284 -> 45136 B

// == KA: LN + W_in GEMM + conv/SiLU + x_proj + dt + CHUNK SCAN SUMMARY =======
// grid = 32 seq * 32 chunks (32 tokens + 3 halo), block = 128, dynamic smem
__global__ void __launch_bounds__(128, 5) kA_front(
    const float* __restrict__ x0, const float* __restrict__ x1,
    const float* __restrict__ x2, const float* __restrict__ x3,
    const float* __restrict__ ga, const float* __restrict__ gb,
    const float* __restrict__ gc, const float* __restrict__ gd,
    const float* __restrict__ ba, const float* __restrict__ bb,
    const float* __restrict__ bc_, const float* __restrict__ bd,
    const float* __restrict__ W_in,
    const float* __restrict__ W_conv, const float* __restrict__ b_conv,
    const float* __restrict__ W_xproj, const float* __restrict__ W_dt,
    const float* __restrict__ b_dt, const float* __restrict__ A_log)
{
    extern __shared__ float sm[];
    float* xs    = sm + OFF_XS;
    float* stat  = sm + OFF_STAT;
    float* Wq    = sm + OFF_WQ;
    float* Wxp   = sm + OFF_WX;
    float* res36 = sm + OFF_R36;
    float* xis   = sm + OFF_XIS;

    int tid = threadIdx.x;
    int blk = blockIdx.x;
    int seq = blk >> 5;
    int ck  = blk & 31;
    int l0  = ck * 32;
    int br  = seq >> 3;
    int b   = seq & 7;

    const float* xp = (br == 0) ? x0 : (br == 1) ? x1 : (br == 2) ? x2 : x3;
    const float* gp = (br == 0) ? ga : (br == 1) ? gb : (br == 2) ? gc : gd;
    const float* bp = (br == 0) ? ba : (br == 1) ? bb : (br == 2) ? bc_ : bd;

    for (int idx = tid; idx < 35*64; idx += 128) {
        int t = idx % 35, c = idx / 35;
        int tl = l0 - 3 + t;
        xs[t*XS_PITCH + c] = (tl >= 0) ? xp[(size_t)(b*64 + c)*1024 + tl] : 0.f;
    }
    __syncthreads();
    if (tid < 35) {
        float s = 0.f, s2 = 0.f;
        #pragma unroll 8
        for (int c = 0; c < 64; c++) { float v = xs[tid*XS_PITCH + c]; s += v; s2 += v*v; }
        float m = s * (1.0f/64.0f);
        float var = s2 * (1.0f/64.0f) - m*m;
        stat[tid*2]   = m;
        stat[tid*2+1] = rsqrtf(var + 1e-5f);
    }
    __syncthreads();
    for (int idx = tid; idx < 35*64; idx += 128) {
        int c = idx & 63, t = idx >> 6;
        float v = (xs[t*XS_PITCH + c] - stat[t*2]) * stat[t*2+1] * gp[c] + bp[c];
        xs[t*XS_PITCH + c] = v;
        if (t >= 3) g_xn[(size_t)(seq*1024 + l0 - 3 + t)*64 + c] = v;
    }

    int tg = tid >> 5, jg = tid & 31;

    // ---- W_in GEMM in 4 quarters of 64 output rows; f32x2-packed over k ----
    #pragma unroll 1
    for (int q = 0; q < 4; q++) {
        __syncthreads();
        {
            const float4* Wg = (const float4*)(W_in + (size_t)q*64*64);
            #pragma unroll
            for (int r = 0; r < 8; r++) {
                int idx = r*128 + tid;
                int j = idx >> 4, c4 = idx & 15;
                *(float4*)&Wq[j*XS_PITCH + c4*4] = Wg[j*16 + c4];
            }
        }
        __syncthreads();

        if (q < 2) {
            int t0 = tg * 9;
            int nt = (tg < 3) ? 9 : 8;
            u64 acc[9][2];
            #pragma unroll
            for (int i = 0; i < 9; i++) { acc[i][0] = 0ull; acc[i][1] = 0ull; }
            #pragma unroll 2
            for (int k4 = 0; k4 < 16; k4++) {
                ulonglong2 w0 = *(const ulonglong2*)&Wq[jg*XS_PITCH + k4*4];
                ulonglong2 w1 = *(const ulonglong2*)&Wq[(jg+32)*XS_PITCH + k4*4];
                #pragma unroll
                for (int i = 0; i < 9; i++) {
                    int t = t0 + i; if (t > 34) t = 34;
                    ulonglong2 xv = *(const ulonglong2*)&xs[t*XS_PITCH + k4*4];
                    acc[i][0] = fma2(xv.x, w0.x, acc[i][0]);
                    acc[i][0] = fma2(xv.y, w0.y, acc[i][0]);
                    acc[i][1] = fma2(xv.x, w1.x, acc[i][1]);
                    acc[i][1] = fma2(xv.y, w1.y, acc[i][1]);
                }
            }
            for (int i = 0; i < 9; i++) {
                int t = t0 + i;
                if (i < nt) {
                    bool valid = (l0 - 3 + t) >= 0;
                    xis[t*XI_PITCH + q*64 + jg]      = valid ? hsum2(acc[i][0]) : 0.f;
                    xis[t*XI_PITCH + q*64 + jg + 32] = valid ? hsum2(acc[i][1]) : 0.f;
                }
            }
        } else {
            int t0 = 3 + tg * 8;
            u64 acc[8][2];
            #pragma unroll
            for (int i = 0; i < 8; i++) { acc[i][0] = 0ull; acc[i][1] = 0ull; }
            #pragma unroll 2
            for (int k4 = 0; k4 < 16; k4++) {
                ulonglong2 w0 = *(const ulonglong2*)&Wq[jg*XS_PITCH + k4*4];
                ulonglong2 w1 = *(const ulonglong2*)&Wq[(jg+32)*XS_PITCH + k4*4];
                #pragma unroll
                for (int i = 0; i < 8; i++) {
                    ulonglong2 xv = *(const ulonglong2*)&xs[(t0+i)*XS_PITCH + k4*4];
                    acc[i][0] = fma2(xv.x, w0.x, acc[i][0]);
                    acc[i][0] = fma2(xv.y, w0.y, acc[i][0]);
                    acc[i][1] = fma2(xv.x, w1.x, acc[i][1]);
                    acc[i][1] = fma2(xv.y, w1.y, acc[i][1]);
                }
            }
            #pragma unroll
            for (int i = 0; i < 8; i++) {
                int tt = tg*8 + i;
                g_z[(size_t)(seq*1024 + l0 + tt)*128 + (q-2)*64 + jg]      = hsum2(acc[i][0]);
                g_z[(size_t)(seq*1024 + l0 + tt)*128 + (q-2)*64 + jg + 32] = hsum2(acc[i][1]);
            }
        }
    }
    __syncthreads();

    // ---- conv4 + SiLU, in place with rolling registers ----
    {
        int d = tid;
        float wc0 = W_conv[d*4+0], wc1 = W_conv[d*4+1], wc2 = W_conv[d*4+2], wc3 = W_conv[d*4+3];
        float bcv = b_conv[d];
        float r0 = xis[0*XI_PITCH + d];
        float r1 = xis[1*XI_PITCH + d];
        float r2 = xis[2*XI_PITCH + d];
        float r3 = xis[3*XI_PITCH + d];
        #pragma unroll 4
        for (int t = 0; t < 32; t++) {
            float v = bcv + wc0*r0 + wc1*r1 + wc2*r2 + wc3*r3;
            v = siluf(v);
            xis[t*XI_PITCH + d] = v;
            g_xc[(size_t)(seq*1024 + l0 + t)*128 + d] = v;
            r0 = r1; r1 = r2; r2 = r3;
            if (t < 31) r3 = xis[(t+4)*XI_PITCH + d];
        }
    }
    {
        const float4* Wg = (const float4*)W_xproj;
        for (int idx = tid; idx < 36*32; idx += 128) {
            int j = idx >> 5, d4 = idx & 31;
            *(float4*)&Wxp[j*132 + d4*4] = Wg[j*32 + d4];
        }
    }
    __syncthreads();

    // ---- x_proj: lane = output column, warp = 8 tokens, f32x2 over dd ----
    {
        int wd = tid >> 5, jx = tid & 31;
        int t0 = wd * 8;
        u64 acc[8][2];
        #pragma unroll
        for (int i = 0; i < 8; i++) { acc[i][0] = 0ull; acc[i][1] = 0ull; }
        bool hi = (jx < 4);
        #pragma unroll 4
        for (int d4 = 0; d4 < 32; d4++) {
            ulonglong2 w0 = *(const ulonglong2*)&Wxp[jx*132 + d4*4];
            ulonglong2 w1 = make_ulonglong2(0ull, 0ull);
            if (hi) w1 = *(const ulonglong2*)&Wxp[(32 + jx)*132 + d4*4];
            #pragma unroll
            for (int i = 0; i < 8; i++) {
                ulonglong2 xv = *(const ulonglong2*)&xis[(t0 + i)*XI_PITCH + d4*4];
                acc[i][0] = fma2(xv.x, w0.x, acc[i][0]);
                acc[i][0] = fma2(xv.y, w0.y, acc[i][0]);
                if (hi) {
                    acc[i][1] = fma2(xv.x, w1.x, acc[i][1]);
                    acc[i][1] = fma2(xv.y, w1.y, acc[i][1]);
                }
            }
        }
        #pragma unroll
        for (int i = 0; i < 8; i++) {
            res36[(t0 + i)*36 + jx] = hsum2(acc[i][0]);
            if (hi) res36[(t0 + i)*36 + 32 + jx] = hsum2(acc[i][1]);
        }
    }
    __syncthreads();

    // ---- fused: dt(softplus) + chunk scan summary (h0 = 0), f32x2-packed ---
    {
        int d = tid;
        float wd0 = W_dt[d*4+0], wd1 = W_dt[d*4+1], wd2 = W_dt[d*4+2], wd3 = W_dt[d*4+3];
        float bdv = b_dt[d];
        float a2[16];
        #pragma unroll
        for (int s = 0; s < 16; s++) a2[s] = -__expf(A_log[d*16 + s]) * LOG2E;
        bool fast = ratio_fast(a2);
        float sdt = 0.f;
        size_t base = ((size_t)(seq*NCHK + ck)*128 + d)*16;

        if (fast) {
            u64 h2[8];
            #pragma unroll
            for (int j = 0; j < 8; j++) h2[j] = 0ull;
            for (int t = 0; t < 32; t++) {
                float4 r0 = *(const float4*)&res36[t*36];
                float raw = bdv + wd0*r0.x + wd1*r0.y + wd2*r0.z + wd3*r0.w;
                float sp = softplusf(raw);
                g_dt[(size_t)(seq*1024 + l0 + t)*128 + d] = sp;
                sdt += sp;
                float dx = sp * xis[t*XI_PITCH + d];
                u64 dx2 = pack2(dx, dx);
                float p = ex2f(sp * a2[0]);
                float p2 = p * p;
                u64 dA = pack2(p, p2);
                u64 qq = pack2(p2, p2);
                #pragma unroll
                for (int sq = 0; sq < 4; sq++) {
                    ulonglong2 Bq = *(const ulonglong2*)&res36[t*36 + 4 + sq*4];
                    h2[2*sq] = fma2(dA, h2[2*sq], mul2(dx2, Bq.x));
                    dA = mul2(dA, qq);
                    h2[2*sq + 1] = fma2(dA, h2[2*sq + 1], mul2(dx2, Bq.y));
                    if (sq < 3) dA = mul2(dA, qq);
                }
            }
            float p = ex2f(a2[0] * sdt);
            float dAa[16]; powers16(p, dAa);
            #pragma unroll
            for (int j = 0; j < 4; j++) {
                float x0_, y0_, x1_, y1_;
                unpack2(h2[2*j], x0_, y0_);
                unpack2(h2[2*j + 1], x1_, y1_);
                *(float4*)&g_pend[base + 4*j] = make_float4(x0_, y0_, x1_, y1_);
                *(float4*)&g_dtot[base + 4*j] =
                    make_float4(dAa[4*j], dAa[4*j+1], dAa[4*j+2], dAa[4*j+3]);
            }
        } else {
            float h[16];
            #pragma unroll
            for (int s = 0; s < 16; s++) h[s] = 0.f;
            for (int t = 0; t < 32; t++) {
                float4 r0 = *(const float4*)&res36[t*36];
                float raw = bdv + wd0*r0.x + wd1*r0.y + wd2*r0.z + wd3*r0.w;
                float sp = fmaxf(raw, 0.f) + log1pf(__expf(-fabsf(raw)));
                g_dt[(size_t)(seq*1024 + l0 + t)*128 + d] = sp;
                sdt += sp;
                float dx = sp * xis[t*XI_PITCH + d];
                #pragma unroll
                for (int s = 0; s < 16; s++) {
                    float dA = ex2f(sp * a2[s]);
                    h[s] = fmaf(dA, h[s], dx * res36[t*36 + 4 + s]);
                }
            }
            #pragma unroll
            for (int s = 0; s < 16; s++) {
                g_pend[base + s] = h[s];
                g_dtot[base + s] = ex2f(a2[s] * sdt);
            }
        }
    }

    // ---- B/C scatter ----
    for (int idx = tid; idx < 1024; idx += 128) {
        int tok = idx >> 5, q = idx & 31;
        float v = res36[tok*36 + 4 + q];
        if (q < 16) g_Bm[(size_t)(seq*1024 + l0 + tok)*16 + q]        = v;
        else        g_Cm[(size_t)(seq*1024 + l0 + tok)*16 + (q - 16)] = v;
    }
}

// ============== K4: sequential combine of chunk states ======================
__global__ void __launch_bounds__(256) k4_combine()
{
    int blk = blockIdx.x;
    int seq = blk >> 3;
    int pair = (blk & 7) * 256 + threadIdx.x;
    float h = 0.f;
    #pragma unroll
    for (int half = 0; half < 2; half++) {
        float dtv[16], pev[16];
        #pragma unroll
        for (int k = 0; k < 16; k++) {
            size_t o = (size_t)(seq*NCHK + half*16 + k)*2048 + pair;
            dtv[k] = g_dtot[o];
            pev[k] = g_pend[o];
        }
        #pragma unroll
        for (int k = 0; k < 16; k++) {
            g_h0[(size_t)(seq*NCHK + half*16 + k)*2048 + pair] = h;
            h = fmaf(dtv[k], h, pev[k]);
        }
    }
}

// ====== KB: scan + y epilogue + W_out GEMM (2 halves) + direct output =======
// smem layout: region0 [0,4224) = Wsh [32][132] (GEMM) / Bs[512]+Cs[512] (scan)
//              ys [4224, 8448) persists across phases.
#define YS_PITCH 132
#define SMEMB_FLOATS (4224 + 32*YS_PITCH)     // 8448 -> 33792 B
__global__ void __launch_bounds__(128, 6) kB_scan_out(
    const float* __restrict__ A_log, const float* __restrict__ Dp,
    const float* __restrict__ W_out, const float* __restrict__ skip,
    float* __restrict__ out)
{
    extern __shared__ float sm[];
    float* Bs  = sm;                 // [32][16]  (scan phase)
    float* Cs  = sm + 512;           // [32][16]
    float* Wsh = sm;                 // [32 c][132] (GEMM phase, overlays Bs/Cs)
    float* ys  = sm + 4224;          // [32 t][132]

    int tid = threadIdx.x;
    int blk = blockIdx.x;
    int seq = blk >> 5;
    int ck  = blk & 31;
    int c0  = ck * CHKL;
    int br  = seq >> 3;
    int b   = seq & 7;

    for (int idx = tid; idx < CHKL*16; idx += 128) {
        Bs[idx] = g_Bm[(size_t)(seq*1024 + c0)*16 + idx];
        Cs[idx] = g_Cm[(size_t)(seq*1024 + c0)*16 + idx];
    }
    __syncthreads();

    int d = tid;
    float a2[16];
    #pragma unroll
    for (int s = 0; s < 16; s++) a2[s] = -__expf(A_log[d*16 + s]) * LOG2E;
    bool fast = ratio_fast(a2);
    float Dv = Dp[d];

    size_t hb = ((size_t)(seq*NCHK + ck)*128 + d)*16;
    const float* dtp_ = g_dt + (size_t)(seq*1024 + c0)*128 + d;
    const float* xcp_ = g_xc + (size_t)(seq*1024 + c0)*128 + d;
    const float* zp_  = g_z  + (size_t)(seq*1024 + c0)*128 + d;

    if (fast) {
        u64 h2[8];
        #pragma unroll
        for (int j = 0; j < 4; j++) {
            float4 hv = *(const float4*)&g_h0[hb + 4*j];
            h2[2*j]     = pack2(hv.x, hv.y);
            h2[2*j + 1] = pack2(hv.z, hv.w);
        }
        float pdt[4], pxc[4], pz[4];
        #pragma unroll
        for (int j = 0; j < 4; j++) {
            pdt[j] = dtp_[j*128]; pxc[j] = xcp_[j*128]; pz[j] = zp_[j*128];
        }
        for (int t0 = 0; t0 < CHKL; t0 += 4) {
            float ndt[4], nxc[4], nz[4];
            #pragma unroll
            for (int j = 0; j < 4; j++) {
                int tn = t0 + 4 + j;
                if (tn < CHKL) { ndt[j] = dtp_[tn*128]; nxc[j] = xcp_[tn*128]; nz[j] = zp_[tn*128]; }
                else           { ndt[j] = 0.f; nxc[j] = 0.f; nz[j] = 0.f; }
            }
            #pragma unroll
            for (int j = 0; j < 4; j++) {
                int t = t0 + j;
                float dx = pdt[j] * pxc[j];
                u64 dx2 = pack2(dx, dx);
                float p = ex2f(pdt[j] * a2[0]);
                float p2 = p * p;
                u64 dA = pack2(p, p2);
                u64 qq = pack2(p2, p2);
                u64 y2 = 0ull;
                #pragma unroll
                for (int sq = 0; sq < 4; sq++) {
                    ulonglong2 Bq = *(const ulonglong2*)&Bs[t*16 + sq*4];
                    ulonglong2 Cq = *(const ulonglong2*)&Cs[t*16 + sq*4];
                    h2[2*sq] = fma2(dA, h2[2*sq], mul2(dx2, Bq.x));
                    y2 = fma2(h2[2*sq], Cq.x, y2);
                    dA = mul2(dA, qq);
                    h2[2*sq + 1] = fma2(dA, h2[2*sq + 1], mul2(dx2, Bq.y));
                    y2 = fma2(h2[2*sq + 1], Cq.y, y2);
                    if (sq < 3) dA = mul2(dA, qq);
                }
                float y = hsum2(y2);
                ys[t*YS_PITCH + d] = (y + Dv*pxc[j]) * siluf(pz[j]);
            }
            #pragma unroll
            for (int j = 0; j < 4; j++) { pdt[j] = ndt[j]; pxc[j] = nxc[j]; pz[j] = nz[j]; }
        }
    } else {
        float h[16];
        #pragma unroll
        for (int s = 0; s < 16; s++) h[s] = g_h0[hb + s];
        for (int t = 0; t < CHKL; t++) {
            float dtv = dtp_[t*128], xcv = xcp_[t*128], zv = zp_[t*128];
            float dx = dtv * xcv;
            float y = 0.f;
            #pragma unroll
            for (int s = 0; s < 16; s++) {
                float dA = ex2f(dtv * a2[s]);
                h[s] = fmaf(dA, h[s], dx * Bs[t*16 + s]);
                y = fmaf(h[s], Cs[t*16 + s], y);
            }
            ys[t*YS_PITCH + d] = (y + Dv*xcv) * siluf(zv);
        }
    }
    __syncthreads();   // Bs/Cs dead; region becomes Wsh

    // ---- W_out GEMM in 2 halves of 32 output channels; direct stores ------
    float sk = skip[0];
    int tg = tid >> 4, jg = tid & 15;
    #pragma unroll 1
    for (int hf = 0; hf < 2; hf++) {
        {
            const float4* Wg = (const float4*)(W_out + (size_t)hf*32*128);
            for (int idx = tid; idx < 32*32; idx += 128) {
                int c = idx >> 5, k4 = idx & 31;
                *(float4*)&Wsh[c*YS_PITCH + k4*4] = Wg[c*32 + k4];
            }
        }
        __syncthreads();

        u64 acc[4][2];
        #pragma unroll
        for (int i = 0; i < 4; i++) { acc[i][0] = 0ull; acc[i][1] = 0ull; }
        #pragma unroll 2
        for (int k4 = 0; k4 < 32; k4++) {
            ulonglong2 w0 = *(const ulonglong2*)&Wsh[jg*YS_PITCH + k4*4];
            ulonglong2 w1 = *(const ulonglong2*)&Wsh[(jg+16)*YS_PITCH + k4*4];
            #pragma unroll
            for (int i = 0; i < 4; i++) {
                ulonglong2 xv = *(const ulonglong2*)&ys[(tg*4 + i)*YS_PITCH + k4*4];
                acc[i][0] = fma2(xv.x, w0.x, acc[i][0]);
                acc[i][0] = fma2(xv.y, w0.y, acc[i][0]);
                acc[i][1] = fma2(xv.x, w1.x, acc[i][1]);
                acc[i][1] = fma2(xv.y, w1.y, acc[i][1]);
            }
        }
        #pragma unroll
        for (int u = 0; u < 2; u++) {
            int c = hf*32 + jg + 16*u;
            float4 o;
            float* ov = (float*)&o;
            #pragma unroll
            for (int i = 0; i < 4; i++) {
                float xnv = g_xn[(size_t)(seq*1024 + c0 + tg*4 + i)*64 + c];
                ov[i] = hsum2(acc[i][u]) + sk * xnv;
            }
            *(float4*)&out[(size_t)(b*256 + br*64 + c)*1024 + c0 + tg*4] = o;
        }
        __syncthreads();   // Wsh reload safety (half 0 -> half 1)
    }
}

// ============================== launch ======================================
extern "C" void kernel_launch(void* const* d_in, const int* in_sizes, int n_in,
                              void* d_out, int out_size) {
    const float* x0      = (const float*)d_in[0];
    const float* x1      = (const float*)d_in[1];
    const float* x2      = (const float*)d_in[2];
    const float* x3      = (const float*)d_in[3];
    const float* g1      = (const float*)d_in[4];
    const float* be1     = (const float*)d_in[5];
    const float* g2      = (const float*)d_in[6];
    const float* be2     = (const float*)d_in[7];
    const float* g3      = (const float*)d_in[8];
    const float* be3     = (const float*)d_in[9];
    const float* g4      = (const float*)d_in[10];
    const float* be4     = (const float*)d_in[11];
    const float* skip    = (const float*)d_in[12];
    const float* W_in    = (const float*)d_in[13];
    const float* W_conv  = (const float*)d_in[14];
    const float* b_conv  = (const float*)d_in[15];
    const float* W_xproj = (const float*)d_in[16];
    const float* W_dt    = (const float*)d_in[17];
    const float* b_dt    = (const float*)d_in[18];
    const float* A_log   = (const float*)d_in[19];
    const float* Dp      = (const float*)d_in[20];
    const float* W_out   = (const float*)d_in[21];
    float* out = (float*)d_out;

    const int SMEMA = SMEMA_FLOATS * (int)sizeof(float);
    const int SMEMB = SMEMB_FLOATS * (int)sizeof(float);
    static bool configured = false;
    if (!configured) {
        cudaFuncSetAttribute(kA_front,
                             cudaFuncAttributeMaxDynamicSharedMemorySize, SMEMA);
        cudaFuncSetAttribute(kB_scan_out,
                             cudaFuncAttributeMaxDynamicSharedMemorySize, SMEMB);
        configured = true;
    }

    kA_front<<<1024, 128, SMEMA>>>(x0, x1, x2, x3, g1, g2, g3, g4,
                                   be1, be2, be3, be4, W_in,
                                   W_conv, b_conv, W_xproj, W_dt, b_dt, A_log);
    k4_combine<<<256, 256>>>();
    kB_scan_out<<<1024, 128, SMEMB>>>(A_log, Dp, W_out, skip, out);
}

// round 17
// speedup vs baseline: 1.0297x; 1.0297x over previous
#include <cuda_runtime.h>
#include <cuda_bf16.h>

#define LOG2E 1.4426950408889634f

#define NCHK 32
#define CHKL 32

typedef unsigned long long u64;

// ---------------- scratch (__device__ globals; no allocation allowed) -------
__device__ float g_xn  [32*1024*64];
__device__ float g_z   [32*1024*128];
__device__ float g_xc  [32*1024*128];
__device__ float g_dt  [32*1024*128];
__device__ float g_Bm  [32*1024*16];
__device__ float g_Cm  [32*1024*16];
__device__ float g_pend[32*NCHK*128*16];
__device__ float g_dtot[32*NCHK*128*16];
__device__ float g_h0  [32*NCHK*128*16];

__device__ __forceinline__ float ex2f(float x) {
    float r; asm("ex2.approx.f32 %0, %1;" : "=f"(r) : "f"(x)); return r;
}
__device__ __forceinline__ float siluf(float x) {
    return x / (1.0f + __expf(-x));
}
__device__ __forceinline__ float softplusf(float x) {
    return fmaxf(x, 0.f) + __logf(1.0f + __expf(-fabsf(x)));
}
__device__ __forceinline__ u64 fma2(u64 a, u64 b, u64 c) {
    u64 d; asm("fma.rn.f32x2 %0, %1, %2, %3;" : "=l"(d) : "l"(a), "l"(b), "l"(c)); return d;
}
__device__ __forceinline__ u64 mul2(u64 a, u64 b) {
    u64 d; asm("mul.rn.f32x2 %0, %1, %2;" : "=l"(d) : "l"(a), "l"(b)); return d;
}
__device__ __forceinline__ u64 pack2(float x, float y) {
    u64 r; asm("mov.b64 %0, {%1, %2};" : "=l"(r) : "f"(x), "f"(y)); return r;
}
__device__ __forceinline__ void unpack2(u64 v, float& x, float& y) {
    asm("mov.b64 {%0, %1}, %2;" : "=f"(x), "=f"(y) : "l"(v));
}
__device__ __forceinline__ float hsum2(u64 v) {
    float x, y; unpack2(v, x, y); return x + y;
}
__device__ __forceinline__ bool ratio_fast(const float* a2) {
    bool ok = true;
    #pragma unroll
    for (int s = 1; s < 16; s++) {
        float want = (float)(s + 1) * a2[0];
        ok = ok && (fabsf(a2[s] - want) <= 1e-3f * fabsf(want));
    }
    return ok;
}
// dA[s] = p^(s+1): exponents of dA[(s-1)>>1] and dA[s>>1] sum to s+1
__device__ __forceinline__ void powers16(float p, float* dA) {
    dA[0] = p;
    #pragma unroll
    for (int s = 1; s < 16; s++) dA[s] = dA[(s-1) >> 1] * dA[s >> 1];
}

// kA smem layout (floats). Two phase-disjoint views of the low region:
//   GEMM phase : xs [35][68] | stat | Wq [64][68]
//   xproj phase: Wxp [36][132] | res36 [32][36]
// xis [35][128] lives above both.
#define XS_PITCH 68
#define XI_PITCH 128
#define OFF_XS    0
#define OFF_STAT  2380
#define OFF_WQ    2452
#define OFF_WX    0
#define OFF_R36   4752
#define OFF_XIS   6804
#define SMEMA_FLOATS (OFF_XIS + 35*XI_PITCH)   // 11284 -> 45136 B

// == KA: LN + W_in GEMM + conv/SiLU + x_proj + dt + CHUNK SCAN SUMMARY =======
// grid = 32 seq * 32 chunks (32 tokens + 3 halo), block = 128, dynamic smem
__global__ void __launch_bounds__(128, 5) kA_front(
    const float* __restrict__ x0, const float* __restrict__ x1,
    const float* __restrict__ x2, const float* __restrict__ x3,
    const float* __restrict__ ga, const float* __restrict__ gb,
    const float* __restrict__ gc, const float* __restrict__ gd,
    const float* __restrict__ ba, const float* __restrict__ bb,
    const float* __restrict__ bc_, const float* __restrict__ bd,
    const float* __restrict__ W_in,
    const float* __restrict__ W_conv, const float* __restrict__ b_conv,
    const float* __restrict__ W_xproj, const float* __restrict__ W_dt,
    const float* __restrict__ b_dt, const float* __restrict__ A_log)
{
    extern __shared__ float sm[];
    float* xs    = sm + OFF_XS;
    float* stat  = sm + OFF_STAT;
    float* Wq    = sm + OFF_WQ;
    float* Wxp   = sm + OFF_WX;
    float* res36 = sm + OFF_R36;
    float* xis   = sm + OFF_XIS;

    int tid = threadIdx.x;
    int blk = blockIdx.x;
    int seq = blk >> 5;
    int ck  = blk & 31;
    int l0  = ck * 32;
    int br  = seq >> 3;
    int b   = seq & 7;

    const float* xp = (br == 0) ? x0 : (br == 1) ? x1 : (br == 2) ? x2 : x3;
    const float* gp = (br == 0) ? ga : (br == 1) ? gb : (br == 2) ? gc : gd;
    const float* bp = (br == 0) ? ba : (br == 1) ? bb : (br == 2) ? bc_ : bd;

    for (int idx = tid; idx < 35*64; idx += 128) {
        int t = idx % 35, c = idx / 35;
        int tl = l0 - 3 + t;
        xs[t*XS_PITCH + c] = (tl >= 0) ? xp[(size_t)(b*64 + c)*1024 + tl] : 0.f;
    }
    __syncthreads();
    if (tid < 35) {
        float s = 0.f, s2 = 0.f;
        #pragma unroll 8
        for (int c = 0; c < 64; c++) { float v = xs[tid*XS_PITCH + c]; s += v; s2 += v*v; }
        float m = s * (1.0f/64.0f);
        float var = s2 * (1.0f/64.0f) - m*m;
        stat[tid*2]   = m;
        stat[tid*2+1] = rsqrtf(var + 1e-5f);
    }
    __syncthreads();
    for (int idx = tid; idx < 35*64; idx += 128) {
        int c = idx & 63, t = idx >> 6;
        float v = (xs[t*XS_PITCH + c] - stat[t*2]) * stat[t*2+1] * gp[c] + bp[c];
        xs[t*XS_PITCH + c] = v;
        if (t >= 3) g_xn[(size_t)(seq*1024 + l0 - 3 + t)*64 + c] = v;
    }

    int tg = tid >> 5, jg = tid & 31;

    // ---- W_in GEMM in 4 quarters of 64 output rows; f32x2-packed over k ----
    #pragma unroll 1
    for (int q = 0; q < 4; q++) {
        __syncthreads();
        {
            const float4* Wg = (const float4*)(W_in + (size_t)q*64*64);
            #pragma unroll
            for (int r = 0; r < 8; r++) {
                int idx = r*128 + tid;
                int j = idx >> 4, c4 = idx & 15;
                *(float4*)&Wq[j*XS_PITCH + c4*4] = Wg[j*16 + c4];
            }
        }
        __syncthreads();

        if (q < 2) {
            int t0 = tg * 9;
            int nt = (tg < 3) ? 9 : 8;
            u64 acc[9][2];
            #pragma unroll
            for (int i = 0; i < 9; i++) { acc[i][0] = 0ull; acc[i][1] = 0ull; }
            #pragma unroll 4
            for (int k4 = 0; k4 < 16; k4++) {
                ulonglong2 w0 = *(const ulonglong2*)&Wq[jg*XS_PITCH + k4*4];
                ulonglong2 w1 = *(const ulonglong2*)&Wq[(jg+32)*XS_PITCH + k4*4];
                #pragma unroll
                for (int i = 0; i < 9; i++) {
                    int t = t0 + i; if (t > 34) t = 34;
                    ulonglong2 xv = *(const ulonglong2*)&xs[t*XS_PITCH + k4*4];
                    acc[i][0] = fma2(xv.x, w0.x, acc[i][0]);
                    acc[i][0] = fma2(xv.y, w0.y, acc[i][0]);
                    acc[i][1] = fma2(xv.x, w1.x, acc[i][1]);
                    acc[i][1] = fma2(xv.y, w1.y, acc[i][1]);
                }
            }
            for (int i = 0; i < 9; i++) {
                int t = t0 + i;
                if (i < nt) {
                    bool valid = (l0 - 3 + t) >= 0;
                    xis[t*XI_PITCH + q*64 + jg]      = valid ? hsum2(acc[i][0]) : 0.f;
                    xis[t*XI_PITCH + q*64 + jg + 32] = valid ? hsum2(acc[i][1]) : 0.f;
                }
            }
        } else {
            int t0 = 3 + tg * 8;
            u64 acc[8][2];
            #pragma unroll
            for (int i = 0; i < 8; i++) { acc[i][0] = 0ull; acc[i][1] = 0ull; }
            #pragma unroll 4
            for (int k4 = 0; k4 < 16; k4++) {
                ulonglong2 w0 = *(const ulonglong2*)&Wq[jg*XS_PITCH + k4*4];
                ulonglong2 w1 = *(const ulonglong2*)&Wq[(jg+32)*XS_PITCH + k4*4];
                #pragma unroll
                for (int i = 0; i < 8; i++) {
                    ulonglong2 xv = *(const ulonglong2*)&xs[(t0+i)*XS_PITCH + k4*4];
                    acc[i][0] = fma2(xv.x, w0.x, acc[i][0]);
                    acc[i][0] = fma2(xv.y, w0.y, acc[i][0]);
                    acc[i][1] = fma2(xv.x, w1.x, acc[i][1]);
                    acc[i][1] = fma2(xv.y, w1.y, acc[i][1]);
                }
            }
            #pragma unroll
            for (int i = 0; i < 8; i++) {
                int tt = tg*8 + i;
                g_z[(size_t)(seq*1024 + l0 + tt)*128 + (q-2)*64 + jg]      = hsum2(acc[i][0]);
                g_z[(size_t)(seq*1024 + l0 + tt)*128 + (q-2)*64 + jg + 32] = hsum2(acc[i][1]);
            }
        }
    }
    __syncthreads();

    // ---- conv4 + SiLU, in place with rolling registers ----
    {
        int d = tid;
        float wc0 = W_conv[d*4+0], wc1 = W_conv[d*4+1], wc2 = W_conv[d*4+2], wc3 = W_conv[d*4+3];
        float bcv = b_conv[d];
        float r0 = xis[0*XI_PITCH + d];
        float r1 = xis[1*XI_PITCH + d];
        float r2 = xis[2*XI_PITCH + d];
        float r3 = xis[3*XI_PITCH + d];
        #pragma unroll 4
        for (int t = 0; t < 32; t++) {
            float v = bcv + wc0*r0 + wc1*r1 + wc2*r2 + wc3*r3;
            v = siluf(v);
            xis[t*XI_PITCH + d] = v;
            g_xc[(size_t)(seq*1024 + l0 + t)*128 + d] = v;
            r0 = r1; r1 = r2; r2 = r3;
            if (t < 31) r3 = xis[(t+4)*XI_PITCH + d];
        }
    }
    {
        const float4* Wg = (const float4*)W_xproj;
        for (int idx = tid; idx < 36*32; idx += 128) {
            int j = idx >> 5, d4 = idx & 31;
            *(float4*)&Wxp[j*132 + d4*4] = Wg[j*32 + d4];
        }
    }
    __syncthreads();

    // ---- x_proj: lane = output column, warp = 8 tokens, f32x2 over dd ----
    {
        int wd = tid >> 5, jx = tid & 31;
        int t0 = wd * 8;
        u64 acc[8][2];
        #pragma unroll
        for (int i = 0; i < 8; i++) { acc[i][0] = 0ull; acc[i][1] = 0ull; }
        bool hi = (jx < 4);
        #pragma unroll 4
        for (int d4 = 0; d4 < 32; d4++) {
            ulonglong2 w0 = *(const ulonglong2*)&Wxp[jx*132 + d4*4];
            ulonglong2 w1 = make_ulonglong2(0ull, 0ull);
            if (hi) w1 = *(const ulonglong2*)&Wxp[(32 + jx)*132 + d4*4];
            #pragma unroll
            for (int i = 0; i < 8; i++) {
                ulonglong2 xv = *(const ulonglong2*)&xis[(t0 + i)*XI_PITCH + d4*4];
                acc[i][0] = fma2(xv.x, w0.x, acc[i][0]);
                acc[i][0] = fma2(xv.y, w0.y, acc[i][0]);
                if (hi) {
                    acc[i][1] = fma2(xv.x, w1.x, acc[i][1]);
                    acc[i][1] = fma2(xv.y, w1.y, acc[i][1]);
                }
            }
        }
        #pragma unroll
        for (int i = 0; i < 8; i++) {
            res36[(t0 + i)*36 + jx] = hsum2(acc[i][0]);
            if (hi) res36[(t0 + i)*36 + 32 + jx] = hsum2(acc[i][1]);
        }
    }
    __syncthreads();

    // ---- fused: dt(softplus) + chunk scan summary (h0 = 0), f32x2-packed ---
    {
        int d = tid;
        float wd0 = W_dt[d*4+0], wd1 = W_dt[d*4+1], wd2 = W_dt[d*4+2], wd3 = W_dt[d*4+3];
        float bdv = b_dt[d];
        float a2[16];
        #pragma unroll
        for (int s = 0; s < 16; s++) a2[s] = -__expf(A_log[d*16 + s]) * LOG2E;
        bool fast = ratio_fast(a2);
        float sdt = 0.f;
        size_t base = ((size_t)(seq*NCHK + ck)*128 + d)*16;

        if (fast) {
            u64 h2[8];
            #pragma unroll
            for (int j = 0; j < 8; j++) h2[j] = 0ull;
            for (int t = 0; t < 32; t++) {
                float4 r0 = *(const float4*)&res36[t*36];
                float raw = bdv + wd0*r0.x + wd1*r0.y + wd2*r0.z + wd3*r0.w;
                float sp = softplusf(raw);
                g_dt[(size_t)(seq*1024 + l0 + t)*128 + d] = sp;
                sdt += sp;
                float dx = sp * xis[t*XI_PITCH + d];
                u64 dx2 = pack2(dx, dx);
                float p = ex2f(sp * a2[0]);
                float p2 = p * p;
                u64 dA = pack2(p, p2);
                u64 qq = pack2(p2, p2);
                #pragma unroll
                for (int sq = 0; sq < 4; sq++) {
                    ulonglong2 Bq = *(const ulonglong2*)&res36[t*36 + 4 + sq*4];
                    h2[2*sq] = fma2(dA, h2[2*sq], mul2(dx2, Bq.x));
                    dA = mul2(dA, qq);
                    h2[2*sq + 1] = fma2(dA, h2[2*sq + 1], mul2(dx2, Bq.y));
                    if (sq < 3) dA = mul2(dA, qq);
                }
            }
            float p = ex2f(a2[0] * sdt);
            float dAa[16]; powers16(p, dAa);
            #pragma unroll
            for (int j = 0; j < 4; j++) {
                float x0_, y0_, x1_, y1_;
                unpack2(h2[2*j], x0_, y0_);
                unpack2(h2[2*j + 1], x1_, y1_);
                *(float4*)&g_pend[base + 4*j] = make_float4(x0_, y0_, x1_, y1_);
                *(float4*)&g_dtot[base + 4*j] =
                    make_float4(dAa[4*j], dAa[4*j+1], dAa[4*j+2], dAa[4*j+3]);
            }
        } else {
            float h[16];
            #pragma unroll
            for (int s = 0; s < 16; s++) h[s] = 0.f;
            for (int t = 0; t < 32; t++) {
                float4 r0 = *(const float4*)&res36[t*36];
                float raw = bdv + wd0*r0.x + wd1*r0.y + wd2*r0.z + wd3*r0.w;
                float sp = fmaxf(raw, 0.f) + log1pf(__expf(-fabsf(raw)));
                g_dt[(size_t)(seq*1024 + l0 + t)*128 + d] = sp;
                sdt += sp;
                float dx = sp * xis[t*XI_PITCH + d];
                #pragma unroll
                for (int s = 0; s < 16; s++) {
                    float dA = ex2f(sp * a2[s]);
                    h[s] = fmaf(dA, h[s], dx * res36[t*36 + 4 + s]);
                }
            }
            #pragma unroll
            for (int s = 0; s < 16; s++) {
                g_pend[base + s] = h[s];
                g_dtot[base + s] = ex2f(a2[s] * sdt);
            }
        }
    }

    // ---- B/C scatter ----
    for (int idx = tid; idx < 1024; idx += 128) {
        int tok = idx >> 5, q = idx & 31;
        float v = res36[tok*36 + 4 + q];
        if (q < 16) g_Bm[(size_t)(seq*1024 + l0 + tok)*16 + q]        = v;
        else        g_Cm[(size_t)(seq*1024 + l0 + tok)*16 + (q - 16)] = v;
    }
}

// ============== K4: sequential combine of chunk states ======================
__global__ void __launch_bounds__(256) k4_combine()
{
    int blk = blockIdx.x;
    int seq = blk >> 3;
    int pair = (blk & 7) * 256 + threadIdx.x;
    float h = 0.f;
    #pragma unroll
    for (int half = 0; half < 2; half++) {
        float dtv[16], pev[16];
        #pragma unroll
        for (int k = 0; k < 16; k++) {
            size_t o = (size_t)(seq*NCHK + half*16 + k)*2048 + pair;
            dtv[k] = g_dtot[o];
            pev[k] = g_pend[o];
        }
        #pragma unroll
        for (int k = 0; k < 16; k++) {
            g_h0[(size_t)(seq*NCHK + half*16 + k)*2048 + pair] = h;
            h = fmaf(dtv[k], h, pev[k]);
        }
    }
}

// ====== KB: scan + y epilogue + W_out GEMM (2 halves) + direct output =======
// R15 configuration: separate regions, 5 blocks/SM.
#define YS_PITCH 132
#define SMEMB_FLOATS (CHKL*16*2 + 32*YS_PITCH + 32*YS_PITCH)   // 9472 -> 37888 B
__global__ void __launch_bounds__(128, 5) kB_scan_out(
    const float* __restrict__ A_log, const float* __restrict__ Dp,
    const float* __restrict__ W_out, const float* __restrict__ skip,
    float* __restrict__ out)
{
    extern __shared__ float sm[];
    float* Bs  = sm;                 // [32][16]
    float* Cs  = Bs + CHKL*16;       // [32][16]
    float* ys  = Cs + CHKL*16;       // [32 t][132]
    float* Wsh = ys + 32*YS_PITCH;   // [32 c][132] (one half of W_out, k contig)

    int tid = threadIdx.x;
    int blk = blockIdx.x;
    int seq = blk >> 5;
    int ck  = blk & 31;
    int c0  = ck * CHKL;
    int br  = seq >> 3;
    int b   = seq & 7;

    for (int idx = tid; idx < CHKL*16; idx += 128) {
        Bs[idx] = g_Bm[(size_t)(seq*1024 + c0)*16 + idx];
        Cs[idx] = g_Cm[(size_t)(seq*1024 + c0)*16 + idx];
    }
    __syncthreads();

    int d = tid;
    float a2[16];
    #pragma unroll
    for (int s = 0; s < 16; s++) a2[s] = -__expf(A_log[d*16 + s]) * LOG2E;
    bool fast = ratio_fast(a2);
    float Dv = Dp[d];

    size_t hb = ((size_t)(seq*NCHK + ck)*128 + d)*16;
    const float* dtp_ = g_dt + (size_t)(seq*1024 + c0)*128 + d;
    const float* xcp_ = g_xc + (size_t)(seq*1024 + c0)*128 + d;
    const float* zp_  = g_z  + (size_t)(seq*1024 + c0)*128 + d;

    if (fast) {
        u64 h2[8];
        #pragma unroll
        for (int j = 0; j < 4; j++) {
            float4 hv = *(const float4*)&g_h0[hb + 4*j];
            h2[2*j]     = pack2(hv.x, hv.y);
            h2[2*j + 1] = pack2(hv.z, hv.w);
        }
        float pdt[4], pxc[4], pz[4];
        #pragma unroll
        for (int j = 0; j < 4; j++) {
            pdt[j] = dtp_[j*128]; pxc[j] = xcp_[j*128]; pz[j] = zp_[j*128];
        }
        for (int t0 = 0; t0 < CHKL; t0 += 4) {
            float ndt[4], nxc[4], nz[4];
            #pragma unroll
            for (int j = 0; j < 4; j++) {
                int tn = t0 + 4 + j;
                if (tn < CHKL) { ndt[j] = dtp_[tn*128]; nxc[j] = xcp_[tn*128]; nz[j] = zp_[tn*128]; }
                else           { ndt[j] = 0.f; nxc[j] = 0.f; nz[j] = 0.f; }
            }
            #pragma unroll
            for (int j = 0; j < 4; j++) {
                int t = t0 + j;
                float dx = pdt[j] * pxc[j];
                u64 dx2 = pack2(dx, dx);
                float p = ex2f(pdt[j] * a2[0]);
                float p2 = p * p;
                u64 dA = pack2(p, p2);
                u64 qq = pack2(p2, p2);
                ulonglong2 Bq0 = *(const ulonglong2*)&Bs[t*16];
                ulonglong2 Bq1 = *(const ulonglong2*)&Bs[t*16 + 4];
                ulonglong2 Bq2 = *(const ulonglong2*)&Bs[t*16 + 8];
                ulonglong2 Bq3 = *(const ulonglong2*)&Bs[t*16 + 12];
                ulonglong2 Cq0 = *(const ulonglong2*)&Cs[t*16];
                ulonglong2 Cq1 = *(const ulonglong2*)&Cs[t*16 + 4];
                ulonglong2 Cq2 = *(const ulonglong2*)&Cs[t*16 + 8];
                ulonglong2 Cq3 = *(const ulonglong2*)&Cs[t*16 + 12];
                u64 Bv[8] = {Bq0.x, Bq0.y, Bq1.x, Bq1.y, Bq2.x, Bq2.y, Bq3.x, Bq3.y};
                u64 Cv[8] = {Cq0.x, Cq0.y, Cq1.x, Cq1.y, Cq2.x, Cq2.y, Cq3.x, Cq3.y};
                u64 y2 = 0ull;
                #pragma unroll
                for (int s = 0; s < 8; s++) {
                    h2[s] = fma2(dA, h2[s], mul2(dx2, Bv[s]));
                    y2 = fma2(h2[s], Cv[s], y2);
                    if (s < 7) dA = mul2(dA, qq);
                }
                float y = hsum2(y2);
                ys[t*YS_PITCH + d] = (y + Dv*pxc[j]) * siluf(pz[j]);
            }
            #pragma unroll
            for (int j = 0; j < 4; j++) { pdt[j] = ndt[j]; pxc[j] = nxc[j]; pz[j] = nz[j]; }
        }
    } else {
        float h[16];
        #pragma unroll
        for (int s = 0; s < 16; s++) h[s] = g_h0[hb + s];
        for (int t = 0; t < CHKL; t++) {
            float dtv = dtp_[t*128], xcv = xcp_[t*128], zv = zp_[t*128];
            float dx = dtv * xcv;
            float y = 0.f;
            #pragma unroll
            for (int s = 0; s < 16; s++) {
                float dA = ex2f(dtv * a2[s]);
                h[s] = fmaf(dA, h[s], dx * Bs[t*16 + s]);
                y = fmaf(h[s], Cs[t*16 + s], y);
            }
            ys[t*YS_PITCH + d] = (y + Dv*xcv) * siluf(zv);
        }
    }
    __syncthreads();

    // ---- W_out GEMM in 2 halves of 32 output channels; direct stores ------
    float sk = skip[0];
    int tg = tid >> 4, jg = tid & 15;
    #pragma unroll 1
    for (int hf = 0; hf < 2; hf++) {
        {
            const float4* Wg = (const float4*)(W_out + (size_t)hf*32*128);
            for (int idx = tid; idx < 32*32; idx += 128) {
                int c = idx >> 5, k4 = idx & 31;
                *(float4*)&Wsh[c*YS_PITCH + k4*4] = Wg[c*32 + k4];
            }
        }
        __syncthreads();

        u64 acc[4][2];
        #pragma unroll
        for (int i = 0; i < 4; i++) { acc[i][0] = 0ull; acc[i][1] = 0ull; }
        #pragma unroll 2
        for (int k4 = 0; k4 < 32; k4++) {
            ulonglong2 w0 = *(const ulonglong2*)&Wsh[jg*YS_PITCH + k4*4];
            ulonglong2 w1 = *(const ulonglong2*)&Wsh[(jg+16)*YS_PITCH + k4*4];
            #pragma unroll
            for (int i = 0; i < 4; i++) {
                ulonglong2 xv = *(const ulonglong2*)&ys[(tg*4 + i)*YS_PITCH + k4*4];
                acc[i][0] = fma2(xv.x, w0.x, acc[i][0]);
                acc[i][0] = fma2(xv.y, w0.y, acc[i][0]);
                acc[i][1] = fma2(xv.x, w1.x, acc[i][1]);
                acc[i][1] = fma2(xv.y, w1.y, acc[i][1]);
            }
        }
        #pragma unroll
        for (int u = 0; u < 2; u++) {
            int c = hf*32 + jg + 16*u;
            float4 o;
            float* ov = (float*)&o;
            #pragma unroll
            for (int i = 0; i < 4; i++) {
                float xnv = g_xn[(size_t)(seq*1024 + c0 + tg*4 + i)*64 + c];
                ov[i] = hsum2(acc[i][u]) + sk * xnv;
            }
            *(float4*)&out[(size_t)(b*256 + br*64 + c)*1024 + c0 + tg*4] = o;
        }
        __syncthreads();   // Wsh reload safety (half 0 -> half 1)
    }
}

// ============================== launch ======================================
extern "C" void kernel_launch(void* const* d_in, const int* in_sizes, int n_in,
                              void* d_out, int out_size) {
    const float* x0      = (const float*)d_in[0];
    const float* x1      = (const float*)d_in[1];
    const float* x2      = (const float*)d_in[2];
    const float* x3      = (const float*)d_in[3];
    const float* g1      = (const float*)d_in[4];
    const float* be1     = (const float*)d_in[5];
    const float* g2      = (const float*)d_in[6];
    const float* be2     = (const float*)d_in[7];
    const float* g3      = (const float*)d_in[8];
    const float* be3     = (const float*)d_in[9];
    const float* g4      = (const float*)d_in[10];
    const float* be4     = (const float*)d_in[11];
    const float* skip    = (const float*)d_in[12];
    const float* W_in    = (const float*)d_in[13];
    const float* W_conv  = (const float*)d_in[14];
    const float* b_conv  = (const float*)d_in[15];
    const float* W_xproj = (const float*)d_in[16];
    const float* W_dt    = (const float*)d_in[17];
    const float* b_dt    = (const float*)d_in[18];
    const float* A_log   = (const float*)d_in[19];
    const float* Dp      = (const float*)d_in[20];
    const float* W_out   = (const float*)d_in[21];
    float* out = (float*)d_out;

    const int SMEMA = SMEMA_FLOATS * (int)sizeof(float);
    const int SMEMB = SMEMB_FLOATS * (int)sizeof(float);
    static bool configured = false;
    if (!configured) {
        cudaFuncSetAttribute(kA_front,
                             cudaFuncAttributeMaxDynamicSharedMemorySize, SMEMA);
        cudaFuncSetAttribute(kB_scan_out,
                             cudaFuncAttributeMaxDynamicSharedMemorySize, SMEMB);
        configured = true;
    }

    kA_front<<<1024, 128, SMEMA>>>(x0, x1, x2, x3, g1, g2, g3, g4,
                                   be1, be2, be3, be4, W_in,
                                   W_conv, b_conv, W_xproj, W_dt, b_dt, A_log);
    k4_combine<<<256, 256>>>();
    kB_scan_out<<<1024, 128, SMEMB>>>(A_log, Dp, W_out, skip, out);
}